// round 13
// baseline (speedup 1.0000x reference)
#include <cuda_runtime.h>
#include <cuda_fp16.h>
#include <cstdint>

// Problem dims (fixed): X:(B,N), boundaries:(N,K+1), weight:(N,K,E), bias:(N,E)
#define BDIM 4096
#define NDIM 64
#define KDIM 128
#define EDIM 512
#define EPS_F 1e-8f
#define NCHUNK 16
#define CHK (KDIM / NCHUNK)          // 8
#define BROW (KDIM + 1)              // 129

// Prefix table T[n][k][e] (fp16): T[n][k][e] = bias[n][e] + sum_{j<k} w[n][j][e]
// out[b][n][e] = relu( lerp(T[n][bidx], T[n][bidx+1], frac) )
__device__ __half g_T16[(size_t)NDIM * BROW * EDIM];
// Per-(b,n) (frac, bidx), indexed b*N+n.
__device__ float2 g_SF[(size_t)BDIM * NDIM];
// Chunk sums: S[n][c][eg2] as float2 (64*16*256 = 2MB)
__device__ float2 g_S2[(size_t)NDIM * NCHUNK * (EDIM / 2)];

#define CHUNK_THREADS (NDIM * NCHUNK * (EDIM / 2))     // 262144
#define CHUNK_BLOCKS  (CHUNK_THREADS / 256)            // 1024
#define SCAN_BLOCKS   CHUNK_BLOCKS                     // 1024
#define SEARCH_PER_T  8
#define SEARCH_BLOCKS ((BDIM * NDIM) / (256 * SEARCH_PER_T))   // 128

// ---------------------------------------------------------------------------
// Setup A: chunk sums at float2 granularity (262144 threads / 1024 blocks —
// 2x the parallelism of the float4 version whose occupancy was grid-limited).
// Thread (n, c, eg2): 8 front-batched float2 loads, sum -> g_S2.
// ---------------------------------------------------------------------------
__global__ void __launch_bounds__(256)
setup_a_kernel(const float* __restrict__ weight) {
    int t = blockIdx.x * blockDim.x + threadIdx.x;
    int eg  = t & 255;            // float2 col: e = 2*eg
    int tmp = t >> 8;             // n*16 + c
    int c   = tmp & 15;
    int n   = tmp >> 4;

    const float2* wp = (const float2*)(weight + (size_t)n * KDIM * EDIM)
                     + (size_t)(c * CHK) * (EDIM / 2) + eg;

    float2 w[CHK];
#pragma unroll
    for (int j = 0; j < CHK; j++)                      // front-batched MLP-8
        w[j] = wp[(size_t)j * (EDIM / 2)];

    float2 s = w[0];
#pragma unroll
    for (int j = 1; j < CHK; j++) { s.x += w[j].x; s.y += w[j].y; }
    g_S2[t] = s;
}

// ---------------------------------------------------------------------------
// Setup B (fused):
//  blocks [0,1024): scan. Thread (n, c, eg2): base = bias + lower chunk sums
//    (15 L2-hot float2 loads, front-batched), 8-step scan over L2-hot weight,
//    packed half2 stores.
//  blocks [1024,1152): amortized staged search. Stage the 33KB boundary
//    table ONCE per block, then 8 coalesced SMEM-only searches per thread.
// ---------------------------------------------------------------------------
__global__ void __launch_bounds__(256)
setup_b_kernel(const float* __restrict__ X,
               const float* __restrict__ bnd,
               const float* __restrict__ weight,
               const float* __restrict__ bias) {
    __shared__ float s_bnd[NDIM * BROW];               // 33KB (search branch)

    if (blockIdx.x < SCAN_BLOCKS) {
        int t = blockIdx.x * blockDim.x + threadIdx.x;
        int eg  = t & 255;
        int tmp = t >> 8;
        int c   = tmp & 15;
        int n   = tmp >> 4;

        const float2* Sp = g_S2 + ((size_t)n * NCHUNK) * (EDIM / 2) + eg;
        const int k0 = c * CHK;
        const float2* wp = (const float2*)(weight + (size_t)n * KDIM * EDIM)
                         + (size_t)k0 * (EDIM / 2) + eg;

        float2 sc[NCHUNK - 1];
#pragma unroll
        for (int cc = 0; cc < NCHUNK - 1; cc++)        // L2-hot, front-batched
            sc[cc] = Sp[(size_t)cc * (EDIM / 2)];

        float2 w[CHK];
#pragma unroll
        for (int j = 0; j < CHK; j++)                  // L2-hot, front-batched
            w[j] = wp[(size_t)j * (EDIM / 2)];

        float2 acc = ((const float2*)(bias + (size_t)n * EDIM))[eg];
#pragma unroll
        for (int cc = 0; cc < NCHUNK - 1; cc++) {
            if (cc < c) { acc.x += sc[cc].x; acc.y += sc[cc].y; }
        }

        unsigned* Tp = (unsigned*)g_T16 + ((size_t)n * BROW + k0) * (EDIM / 2) + eg;
#pragma unroll
        for (int j = 0; j < CHK; j++) {
            __half2 h = __floats2half2_rn(acc.x, acc.y);
            Tp[(size_t)j * (EDIM / 2)] = *(unsigned*)&h;
            acc.x += w[j].x; acc.y += w[j].y;
        }
        if (c == NCHUNK - 1) {
            __half2 h = __floats2half2_rn(acc.x, acc.y);
            Tp[(size_t)CHK * (EDIM / 2)] = *(unsigned*)&h;
        }
    } else {
        // Stage boundary table once (33KB, L2-hot broadcast across blocks)
        for (int j = threadIdx.x; j < NDIM * BROW; j += 256)
            s_bnd[j] = bnd[j];
        __syncthreads();

        const int base = (blockIdx.x - SCAN_BLOCKS) * 256 * SEARCH_PER_T;
#pragma unroll
        for (int j = 0; j < SEARCH_PER_T; j++) {
            const int i = base + j * 256 + threadIdx.x;   // coalesced
            const int n = i & (NDIM - 1);
            const float x = X[i];
            const float* row = s_bnd + n * BROW;

            int lo = 0, len = KDIM - 1;                   // SMEM-only search
            while (len > 0) {
                int half = len >> 1;
                bool pred = row[1 + lo + half] < x;
                lo  += pred ? (half + 1) : 0;
                len  = pred ? (len - half - 1) : half;
            }
            const float s  = row[lo];
            const float eb = row[lo + 1];
            g_SF[i] = make_float2((x - s) / (eb - s + EPS_F), __int_as_float(lo));
        }
    }
}

// ---------------------------------------------------------------------------
// Gather (proven 86us config — UNCHANGED): one warp per (b,n). Front-batched
// table LDG.128s, fp32 lerp, STS to this warp's 2KB SMEM slot, one per-warp
// cp.async.bulk TMA store. __syncwarp only.
// ---------------------------------------------------------------------------
__global__ void gather_kernel(float* __restrict__ out) {
    __shared__ float4 sm[8][EDIM / 4];                 // 8 x 2KB = 16KB

    const int lane = threadIdx.x & 31;
    const int warp = threadIdx.x >> 5;
    const int n = blockIdx.y;
    const int b = blockIdx.x * 8 + warp;

    const float2 sf = __ldg(&g_SF[(size_t)b * NDIM + n]);
    const float frac = sf.x;
    const int   lo   = __float_as_int(sf.y);

    const uint4* T0 = (const uint4*)(g_T16 + ((size_t)n * BROW + lo) * EDIM);
    const uint4* T1 = T0 + (EDIM / 8);

    uint4 a0 = __ldg(&T0[lane]);
    uint4 c0 = __ldg(&T1[lane]);
    uint4 a1 = __ldg(&T0[lane + 32]);
    uint4 c1 = __ldg(&T1[lane + 32]);

#pragma unroll
    for (int j = 0; j < 2; j++) {
        const uint4& a  = j ? a1 : a0;
        const uint4& cc = j ? c1 : c0;
        const unsigned* ap = &a.x;
        const unsigned* cp = &cc.x;
        float4 r0, r1;
#pragma unroll
        for (int q = 0; q < 4; q++) {
            float2 av = __half22float2(*(const __half2*)&ap[q]);
            float2 cv = __half22float2(*(const __half2*)&cp[q]);
            float v0 = fmaxf(fmaf(frac, cv.x - av.x, av.x), 0.0f);
            float v1 = fmaxf(fmaf(frac, cv.y - av.y, av.y), 0.0f);
            if (q == 0)      { r0.x = v0; r0.y = v1; }
            else if (q == 1) { r0.z = v0; r0.w = v1; }
            else if (q == 2) { r1.x = v0; r1.y = v1; }
            else             { r1.z = v0; r1.w = v1; }
        }
        const int i = lane + 32 * j;
        sm[warp][2 * i]     = r0;
        sm[warp][2 * i + 1] = r1;
    }

    __syncwarp();

    if (lane == 0) {
        float* gdst = out + ((size_t)b * NDIM + n) * EDIM;
        uint32_t saddr;
        asm("{ .reg .u64 t; cvta.to.shared.u64 t, %1; cvt.u32.u64 %0, t; }"
            : "=r"(saddr) : "l"(&sm[warp][0]));
        asm volatile("fence.proxy.async.shared::cta;" ::: "memory");
        asm volatile(
            "cp.async.bulk.global.shared::cta.bulk_group [%0], [%1], %2;"
            :: "l"(gdst), "r"(saddr), "r"((int)(EDIM * 4)) : "memory");
        asm volatile("cp.async.bulk.commit_group;" ::: "memory");
        asm volatile("cp.async.bulk.wait_group 0;" ::: "memory");
    }
}

extern "C" void kernel_launch(void* const* d_in, const int* in_sizes, int n_in,
                              void* d_out, int out_size) {
    const float* X      = (const float*)d_in[0];   // (B, N)
    const float* bnd    = (const float*)d_in[1];   // (N, K+1)
    const float* weight = (const float*)d_in[2];   // (N, K, E)
    const float* bias   = (const float*)d_in[3];   // (N, E)
    float* out = (float*)d_out;                    // (B, N, E)

    setup_a_kernel<<<CHUNK_BLOCKS, 256>>>(weight);
    setup_b_kernel<<<SCAN_BLOCKS + SEARCH_BLOCKS, 256>>>(X, bnd, weight, bias);

    dim3 grid(BDIM / 8, NDIM);
    gather_kernel<<<grid, 256>>>(out);
}

// round 14
// speedup vs baseline: 1.0066x; 1.0066x over previous
#include <cuda_runtime.h>
#include <cuda_fp16.h>
#include <cstdint>

// Problem dims (fixed): X:(B,N), boundaries:(N,K+1), weight:(N,K,E), bias:(N,E)
#define BDIM 4096
#define NDIM 64
#define KDIM 128
#define EDIM 512
#define EPS_F 1e-8f
#define NCHUNK 16
#define CHK (KDIM / NCHUNK)          // 8
#define BROW (KDIM + 1)              // 129

// Prefix table T[n][k][e] (fp16): T[n][k][e] = bias[n][e] + sum_{j<k} w[n][j][e]
// out[b][n][e] = relu( lerp(T[n][bidx], T[n][bidx+1], frac) )
__device__ __half g_T16[(size_t)NDIM * BROW * EDIM];
// Per-(b,n) (frac, bidx), indexed b*N+n.
__device__ float2 g_SF[(size_t)BDIM * NDIM];
// Chunk sums: S[n][c][eg2] as float2 (2MB)
__device__ float2 g_S2[(size_t)NDIM * NCHUNK * (EDIM / 2)];

#define CHUNK_THREADS (NDIM * NCHUNK * (EDIM / 2))     // 262144
#define CHUNK_BLOCKS  (CHUNK_THREADS / 256)            // 1024
#define SEARCH_PER_T  8
#define SEARCH_BLOCKS ((BDIM * NDIM) / (256 * SEARCH_PER_T))   // 128

// ---------------------------------------------------------------------------
// Setup A (fused; search blocks FIRST so they overlap the chunk wave):
//  blocks [0,128): staged search. Stage the 33KB boundary table once, then
//    8 coalesced SMEM-only binary searches per thread -> g_SF.
//  blocks [128,1152): chunk sums (measured 6.8us standalone): thread
//    (n,c,eg2) front-batches 8 float2 loads, sums -> g_S2.
// ---------------------------------------------------------------------------
__global__ void __launch_bounds__(256)
setup_a_kernel(const float* __restrict__ X,
               const float* __restrict__ bnd,
               const float* __restrict__ weight) {
    __shared__ float s_bnd[NDIM * BROW];               // 33KB

    if (blockIdx.x < SEARCH_BLOCKS) {
        for (int j = threadIdx.x; j < NDIM * BROW; j += 256)
            s_bnd[j] = bnd[j];
        __syncthreads();

        const int base = blockIdx.x * 256 * SEARCH_PER_T;
#pragma unroll
        for (int j = 0; j < SEARCH_PER_T; j++) {
            const int i = base + j * 256 + threadIdx.x;   // coalesced X reads
            const int n = i & (NDIM - 1);
            const float x = X[i];
            const float* row = s_bnd + n * BROW;

            int lo = 0, len = KDIM - 1;                   // SMEM-only search
            while (len > 0) {
                int half = len >> 1;
                bool pred = row[1 + lo + half] < x;
                lo  += pred ? (half + 1) : 0;
                len  = pred ? (len - half - 1) : half;
            }
            const float s  = row[lo];
            const float eb = row[lo + 1];
            g_SF[i] = make_float2((x - s) / (eb - s + EPS_F), __int_as_float(lo));
        }
    } else {
        int t = (blockIdx.x - SEARCH_BLOCKS) * 256 + threadIdx.x;
        int eg  = t & 255;            // float2 col: e = 2*eg
        int tmp = t >> 8;             // n*16 + c
        int c   = tmp & 15;
        int n   = tmp >> 4;

        const float2* wp = (const float2*)(weight + (size_t)n * KDIM * EDIM)
                         + (size_t)(c * CHK) * (EDIM / 2) + eg;

        float2 w[CHK];
#pragma unroll
        for (int j = 0; j < CHK; j++)                  // front-batched MLP-8
            w[j] = wp[(size_t)j * (EDIM / 2)];

        float2 s = w[0];
#pragma unroll
        for (int j = 1; j < CHK; j++) { s.x += w[j].x; s.y += w[j].y; }
        g_S2[t] = s;
    }
}

// ---------------------------------------------------------------------------
// Setup B: pure scan (round-8 proven structure, no shared array). Thread
// (n, c, eg2): base = bias + lower chunk sums (front-batched L2-hot loads),
// 8-step scan over L2-hot weight, packed half2 stores.
// ---------------------------------------------------------------------------
__global__ void __launch_bounds__(256)
setup_b_kernel(const float* __restrict__ weight,
               const float* __restrict__ bias) {
    int t = blockIdx.x * blockDim.x + threadIdx.x;
    int eg  = t & 255;
    int tmp = t >> 8;
    int c   = tmp & 15;
    int n   = tmp >> 4;

    const float2* Sp = g_S2 + ((size_t)n * NCHUNK) * (EDIM / 2) + eg;
    const int k0 = c * CHK;
    const float2* wp = (const float2*)(weight + (size_t)n * KDIM * EDIM)
                     + (size_t)k0 * (EDIM / 2) + eg;

    float2 sc[NCHUNK - 1];
#pragma unroll
    for (int cc = 0; cc < NCHUNK - 1; cc++)            // L2-hot, front-batched
        sc[cc] = Sp[(size_t)cc * (EDIM / 2)];

    float2 w[CHK];
#pragma unroll
    for (int j = 0; j < CHK; j++)                      // L2-hot, front-batched
        w[j] = wp[(size_t)j * (EDIM / 2)];

    float2 acc = ((const float2*)(bias + (size_t)n * EDIM))[eg];
#pragma unroll
    for (int cc = 0; cc < NCHUNK - 1; cc++) {
        if (cc < c) { acc.x += sc[cc].x; acc.y += sc[cc].y; }
    }

    unsigned* Tp = (unsigned*)g_T16 + ((size_t)n * BROW + k0) * (EDIM / 2) + eg;
#pragma unroll
    for (int j = 0; j < CHK; j++) {
        __half2 h = __floats2half2_rn(acc.x, acc.y);
        Tp[(size_t)j * (EDIM / 2)] = *(unsigned*)&h;
        acc.x += w[j].x; acc.y += w[j].y;
    }
    if (c == NCHUNK - 1) {
        __half2 h = __floats2half2_rn(acc.x, acc.y);
        Tp[(size_t)CHK * (EDIM / 2)] = *(unsigned*)&h;
    }
}

// ---------------------------------------------------------------------------
// Gather (proven 86us config — UNCHANGED): one warp per (b,n). Front-batched
// table LDG.128s, fp32 lerp, STS to this warp's 2KB SMEM slot, one per-warp
// cp.async.bulk TMA store. __syncwarp only.
// ---------------------------------------------------------------------------
__global__ void gather_kernel(float* __restrict__ out) {
    __shared__ float4 sm[8][EDIM / 4];                 // 8 x 2KB = 16KB

    const int lane = threadIdx.x & 31;
    const int warp = threadIdx.x >> 5;
    const int n = blockIdx.y;
    const int b = blockIdx.x * 8 + warp;

    const float2 sf = __ldg(&g_SF[(size_t)b * NDIM + n]);
    const float frac = sf.x;
    const int   lo   = __float_as_int(sf.y);

    const uint4* T0 = (const uint4*)(g_T16 + ((size_t)n * BROW + lo) * EDIM);
    const uint4* T1 = T0 + (EDIM / 8);

    uint4 a0 = __ldg(&T0[lane]);
    uint4 c0 = __ldg(&T1[lane]);
    uint4 a1 = __ldg(&T0[lane + 32]);
    uint4 c1 = __ldg(&T1[lane + 32]);

#pragma unroll
    for (int j = 0; j < 2; j++) {
        const uint4& a  = j ? a1 : a0;
        const uint4& cc = j ? c1 : c0;
        const unsigned* ap = &a.x;
        const unsigned* cp = &cc.x;
        float4 r0, r1;
#pragma unroll
        for (int q = 0; q < 4; q++) {
            float2 av = __half22float2(*(const __half2*)&ap[q]);
            float2 cv = __half22float2(*(const __half2*)&cp[q]);
            float v0 = fmaxf(fmaf(frac, cv.x - av.x, av.x), 0.0f);
            float v1 = fmaxf(fmaf(frac, cv.y - av.y, av.y), 0.0f);
            if (q == 0)      { r0.x = v0; r0.y = v1; }
            else if (q == 1) { r0.z = v0; r0.w = v1; }
            else if (q == 2) { r1.x = v0; r1.y = v1; }
            else             { r1.z = v0; r1.w = v1; }
        }
        const int i = lane + 32 * j;
        sm[warp][2 * i]     = r0;
        sm[warp][2 * i + 1] = r1;
    }

    __syncwarp();

    if (lane == 0) {
        float* gdst = out + ((size_t)b * NDIM + n) * EDIM;
        uint32_t saddr;
        asm("{ .reg .u64 t; cvta.to.shared.u64 t, %1; cvt.u32.u64 %0, t; }"
            : "=r"(saddr) : "l"(&sm[warp][0]));
        asm volatile("fence.proxy.async.shared::cta;" ::: "memory");
        asm volatile(
            "cp.async.bulk.global.shared::cta.bulk_group [%0], [%1], %2;"
            :: "l"(gdst), "r"(saddr), "r"((int)(EDIM * 4)) : "memory");
        asm volatile("cp.async.bulk.commit_group;" ::: "memory");
        asm volatile("cp.async.bulk.wait_group 0;" ::: "memory");
    }
}

extern "C" void kernel_launch(void* const* d_in, const int* in_sizes, int n_in,
                              void* d_out, int out_size) {
    const float* X      = (const float*)d_in[0];   // (B, N)
    const float* bnd    = (const float*)d_in[1];   // (N, K+1)
    const float* weight = (const float*)d_in[2];   // (N, K, E)
    const float* bias   = (const float*)d_in[3];   // (N, E)
    float* out = (float*)d_out;                    // (B, N, E)

    setup_a_kernel<<<SEARCH_BLOCKS + CHUNK_BLOCKS, 256>>>(X, bnd, weight);
    setup_b_kernel<<<CHUNK_BLOCKS, 256>>>(weight, bias);

    dim3 grid(BDIM / 8, NDIM);
    gather_kernel<<<grid, 256>>>(out);
}

// round 15
// speedup vs baseline: 1.0904x; 1.0833x over previous
#include <cuda_runtime.h>
#include <cuda_fp16.h>
#include <cstdint>

// Problem dims (fixed): X:(B,N), boundaries:(N,K+1), weight:(N,K,E), bias:(N,E)
#define BDIM 4096
#define NDIM 64
#define KDIM 128
#define EDIM 512
#define EPS_F 1e-8f
#define NCHUNK 16
#define CHK (KDIM / NCHUNK)          // 8
#define BROW (KDIM + 1)              // 129

// Prefix table T[n][k][e] (fp16): T[n][k][e] = bias[n][e] + sum_{j<k} w[n][j][e]
// out[b][n][e] = relu( lerp(T[n][bidx], T[n][bidx+1], frac) )
__device__ __half g_T16[(size_t)NDIM * BROW * EDIM];
// Per-(b,n) (frac, bidx), indexed b*N+n.
__device__ float2 g_SF[(size_t)BDIM * NDIM];
// Chunk sums: S[n][c][eg2] as float2 (2MB)
__device__ float2 g_S2[(size_t)NDIM * NCHUNK * (EDIM / 2)];

#define CHUNK_THREADS (NDIM * NCHUNK * (EDIM / 2))     // 262144
#define CHUNK_BLOCKS  (CHUNK_THREADS / 256)            // 1024
#define SEARCH_BLOCKS ((BDIM * NDIM) / 256)            // 1024

// ---------------------------------------------------------------------------
// Setup A (fused, NO shared memory anywhere):
//  blocks [0,1024): chunk sums (proven 6.8us): thread (n,c,eg2) front-batches
//    8 float2 loads, sums -> g_S2.
//  blocks [1024,2048): ANALYTIC search: boundaries are a uniform grid, so
//    lo = clamp(ceil(128x)-1). A verification walk against the LOADED values
//    guarantees exact lower_bound semantics regardless (usually 0 steps).
//    ~4 L1-hot loads per pair instead of 9 serial binary-search steps.
// ---------------------------------------------------------------------------
__global__ void __launch_bounds__(256)
setup_a_kernel(const float* __restrict__ X,
               const float* __restrict__ bnd,
               const float* __restrict__ weight) {
    if (blockIdx.x < CHUNK_BLOCKS) {
        int t = blockIdx.x * blockDim.x + threadIdx.x;
        int eg  = t & 255;            // float2 col: e = 2*eg
        int tmp = t >> 8;             // n*16 + c
        int c   = tmp & 15;
        int n   = tmp >> 4;

        const float2* wp = (const float2*)(weight + (size_t)n * KDIM * EDIM)
                         + (size_t)(c * CHK) * (EDIM / 2) + eg;

        float2 w[CHK];
#pragma unroll
        for (int j = 0; j < CHK; j++)                  // front-batched MLP-8
            w[j] = wp[(size_t)j * (EDIM / 2)];

        float2 s = w[0];
#pragma unroll
        for (int j = 1; j < CHK; j++) { s.x += w[j].x; s.y += w[j].y; }
        g_S2[t] = s;
    } else {
        const int i = (blockIdx.x - CHUNK_BLOCKS) * 256 + threadIdx.x; // b*N+n
        const int n = i & (NDIM - 1);
        const float x = X[i];                          // coalesced
        const float* bn = bnd + (size_t)n * BROW;

        // Analytic guess on the uniform grid, then exact verification walk.
        int lo = (int)ceilf(x * (float)KDIM) - 1;
        lo = lo < 0 ? 0 : (lo > KDIM - 1 ? KDIM - 1 : lo);
        // lower_bound invariant: (lo==0 || bn[lo] < x) && (lo==K-1 || bn[lo+1] >= x)
        while (lo < KDIM - 1 && __ldg(&bn[lo + 1]) < x) ++lo;
        while (lo > 0 && __ldg(&bn[lo]) >= x) --lo;

        const float s  = __ldg(&bn[lo]);
        const float eb = __ldg(&bn[lo + 1]);
        g_SF[i] = make_float2((x - s) / (eb - s + EPS_F), __int_as_float(lo));
    }
}

// ---------------------------------------------------------------------------
// Setup B: pure scan (proven 2.6us). Thread (n, c, eg2): base = bias + lower
// chunk sums (front-batched L2-hot loads), 8-step scan over L2-hot weight,
// packed half2 stores.
// ---------------------------------------------------------------------------
__global__ void __launch_bounds__(256)
setup_b_kernel(const float* __restrict__ weight,
               const float* __restrict__ bias) {
    int t = blockIdx.x * blockDim.x + threadIdx.x;
    int eg  = t & 255;
    int tmp = t >> 8;
    int c   = tmp & 15;
    int n   = tmp >> 4;

    const float2* Sp = g_S2 + ((size_t)n * NCHUNK) * (EDIM / 2) + eg;
    const int k0 = c * CHK;
    const float2* wp = (const float2*)(weight + (size_t)n * KDIM * EDIM)
                     + (size_t)k0 * (EDIM / 2) + eg;

    float2 sc[NCHUNK - 1];
#pragma unroll
    for (int cc = 0; cc < NCHUNK - 1; cc++)            // L2-hot, front-batched
        sc[cc] = Sp[(size_t)cc * (EDIM / 2)];

    float2 w[CHK];
#pragma unroll
    for (int j = 0; j < CHK; j++)                      // L2-hot, front-batched
        w[j] = wp[(size_t)j * (EDIM / 2)];

    float2 acc = ((const float2*)(bias + (size_t)n * EDIM))[eg];
#pragma unroll
    for (int cc = 0; cc < NCHUNK - 1; cc++) {
        if (cc < c) { acc.x += sc[cc].x; acc.y += sc[cc].y; }
    }

    unsigned* Tp = (unsigned*)g_T16 + ((size_t)n * BROW + k0) * (EDIM / 2) + eg;
#pragma unroll
    for (int j = 0; j < CHK; j++) {
        __half2 h = __floats2half2_rn(acc.x, acc.y);
        Tp[(size_t)j * (EDIM / 2)] = *(unsigned*)&h;
        acc.x += w[j].x; acc.y += w[j].y;
    }
    if (c == NCHUNK - 1) {
        __half2 h = __floats2half2_rn(acc.x, acc.y);
        Tp[(size_t)CHK * (EDIM / 2)] = *(unsigned*)&h;
    }
}

// ---------------------------------------------------------------------------
// Gather (proven 86us config — UNCHANGED): one warp per (b,n). Front-batched
// table LDG.128s, fp32 lerp, STS to this warp's 2KB SMEM slot, one per-warp
// cp.async.bulk TMA store. __syncwarp only.
// ---------------------------------------------------------------------------
__global__ void gather_kernel(float* __restrict__ out) {
    __shared__ float4 sm[8][EDIM / 4];                 // 8 x 2KB = 16KB

    const int lane = threadIdx.x & 31;
    const int warp = threadIdx.x >> 5;
    const int n = blockIdx.y;
    const int b = blockIdx.x * 8 + warp;

    const float2 sf = __ldg(&g_SF[(size_t)b * NDIM + n]);
    const float frac = sf.x;
    const int   lo   = __float_as_int(sf.y);

    const uint4* T0 = (const uint4*)(g_T16 + ((size_t)n * BROW + lo) * EDIM);
    const uint4* T1 = T0 + (EDIM / 8);

    uint4 a0 = __ldg(&T0[lane]);
    uint4 c0 = __ldg(&T1[lane]);
    uint4 a1 = __ldg(&T0[lane + 32]);
    uint4 c1 = __ldg(&T1[lane + 32]);

#pragma unroll
    for (int j = 0; j < 2; j++) {
        const uint4& a  = j ? a1 : a0;
        const uint4& cc = j ? c1 : c0;
        const unsigned* ap = &a.x;
        const unsigned* cp = &cc.x;
        float4 r0, r1;
#pragma unroll
        for (int q = 0; q < 4; q++) {
            float2 av = __half22float2(*(const __half2*)&ap[q]);
            float2 cv = __half22float2(*(const __half2*)&cp[q]);
            float v0 = fmaxf(fmaf(frac, cv.x - av.x, av.x), 0.0f);
            float v1 = fmaxf(fmaf(frac, cv.y - av.y, av.y), 0.0f);
            if (q == 0)      { r0.x = v0; r0.y = v1; }
            else if (q == 1) { r0.z = v0; r0.w = v1; }
            else if (q == 2) { r1.x = v0; r1.y = v1; }
            else             { r1.z = v0; r1.w = v1; }
        }
        const int i = lane + 32 * j;
        sm[warp][2 * i]     = r0;
        sm[warp][2 * i + 1] = r1;
    }

    __syncwarp();

    if (lane == 0) {
        float* gdst = out + ((size_t)b * NDIM + n) * EDIM;
        uint32_t saddr;
        asm("{ .reg .u64 t; cvta.to.shared.u64 t, %1; cvt.u32.u64 %0, t; }"
            : "=r"(saddr) : "l"(&sm[warp][0]));
        asm volatile("fence.proxy.async.shared::cta;" ::: "memory");
        asm volatile(
            "cp.async.bulk.global.shared::cta.bulk_group [%0], [%1], %2;"
            :: "l"(gdst), "r"(saddr), "r"((int)(EDIM * 4)) : "memory");
        asm volatile("cp.async.bulk.commit_group;" ::: "memory");
        asm volatile("cp.async.bulk.wait_group 0;" ::: "memory");
    }
}

extern "C" void kernel_launch(void* const* d_in, const int* in_sizes, int n_in,
                              void* d_out, int out_size) {
    const float* X      = (const float*)d_in[0];   // (B, N)
    const float* bnd    = (const float*)d_in[1];   // (N, K+1)
    const float* weight = (const float*)d_in[2];   // (N, K, E)
    const float* bias   = (const float*)d_in[3];   // (N, E)
    float* out = (float*)d_out;                    // (B, N, E)

    setup_a_kernel<<<CHUNK_BLOCKS + SEARCH_BLOCKS, 256>>>(X, bnd, weight);
    setup_b_kernel<<<CHUNK_BLOCKS, 256>>>(weight, bias);

    dim3 grid(BDIM / 8, NDIM);
    gather_kernel<<<grid, 256>>>(out);
}